// round 5
// baseline (speedup 1.0000x reference)
#include <cuda_runtime.h>
#include <cuda_bf16.h>

#define FULL 0xffffffffu
typedef unsigned long long u64;

// ---------- packed f32x2 helpers (SASS FFMA2 path, PTX-only) ----------
__device__ __forceinline__ u64 pack2(float x, float y) {
    u64 r; asm("mov.b64 %0, {%1, %2};" : "=l"(r) : "f"(x), "f"(y)); return r;
}
__device__ __forceinline__ float2 unpack2(u64 v) {
    float2 f; asm("mov.b64 {%0, %1}, %2;" : "=f"(f.x), "=f"(f.y) : "l"(v)); return f;
}
__device__ __forceinline__ u64 mul2(u64 a, u64 b) {
    u64 d; asm("mul.rn.f32x2 %0, %1, %2;" : "=l"(d) : "l"(a), "l"(b)); return d;
}
__device__ __forceinline__ u64 fma2(u64 a, u64 b, u64 c) {
    u64 d; asm("fma.rn.f32x2 %0, %1, %2, %3;" : "=l"(d) : "l"(a), "l"(b), "l"(c)); return d;
}

// In-register butterfly on register-bit pb with coefficients (c, s).
// Pair rule (bit=0 elem a, bit=1 elem b): a' = c*a - s*b ; b' = s*a + c*b.
__device__ __forceinline__ void butterfly_reg(u64 a[16], int pb, float2 p) {
    u64 c2  = pack2(p.x,  p.x);
    u64 s2  = pack2(p.y,  p.y);
    u64 ns2 = pack2(-p.y, -p.y);
#pragma unroll
    for (int r = 0; r < 16; r++) {
        if (r & pb) continue;
        int r2 = r | pb;
        u64 t  = mul2(ns2, a[r2]);
        u64 u  = mul2(s2,  a[r]);
        u64 nr = fma2(c2, a[r],  t);
        a[r2]  = fma2(c2, a[r2], u);
        a[r]   = nr;
    }
}

// Exchange register-bit k with lane-bit k (within 16-lane group).
// Amps whose reg-bit != lane-bit move: only half the registers cross lanes.
__device__ __forceinline__ void swap_bit(u64 a[16], int k, int sub) {
    int pb = 1 << k, mask = 1 << k;
    bool hi = (sub & mask) != 0;
#pragma unroll
    for (int r = 0; r < 16; r++) {
        if (r & pb) continue;
        int r2 = r | pb;
        u64 send = hi ? a[r] : a[r2];
        u64 got  = __shfl_xor_sync(FULL, send, mask);
        if (hi) a[r] = got; else a[r2] = got;
    }
}

// Layout A: reg bits [3..0] = d bits [7..4] (wires 0..3),
//           lane bits [3..0] = d bits [3..0] (wires 4..7).
// Layout B: fully swapped (reg = d[3..0], lane = d[7..4]).
// RY1 runs A->B, RY2 runs B->A. All wire rotations commute (distinct bits).
__device__ __forceinline__ void layer_A_to_B(u64 a[16], const float2* cs, int sub) {
    butterfly_reg(a, 8, cs[0]);
    butterfly_reg(a, 4, cs[1]);
    butterfly_reg(a, 2, cs[2]);
    butterfly_reg(a, 1, cs[3]);
    swap_bit(a, 3, sub); butterfly_reg(a, 8, cs[4]);
    swap_bit(a, 2, sub); butterfly_reg(a, 4, cs[5]);
    swap_bit(a, 1, sub); butterfly_reg(a, 2, cs[6]);
    swap_bit(a, 0, sub); butterfly_reg(a, 1, cs[7]);
}
__device__ __forceinline__ void layer_B_to_A(u64 a[16], const float2* cs, int sub) {
    butterfly_reg(a, 8, cs[4]);
    butterfly_reg(a, 4, cs[5]);
    butterfly_reg(a, 2, cs[6]);
    butterfly_reg(a, 1, cs[7]);
    swap_bit(a, 3, sub); butterfly_reg(a, 8, cs[0]);
    swap_bit(a, 2, sub); butterfly_reg(a, 4, cs[1]);
    swap_bit(a, 1, sub); butterfly_reg(a, 2, cs[2]);
    swap_bit(a, 0, sub); butterfly_reg(a, 1, cs[3]);
}

// Single fused kernel: per-block setup in shared memory (params are tiny),
// then 2 states per warp, 16 lanes per state, 16 packed amps per thread.
__global__ __launch_bounds__(128, 8)
void vqc_main(const float* __restrict__ x,
              const float* __restrict__ ry1,  const float* __restrict__ crz1,
              const float* __restrict__ ry2,  const float* __restrict__ crz2,
              float* __restrict__ out, int nstates) {
    // diag tables stored so the lane-varying coord (sub) is the fast index.
    __shared__ u64    s_d1[256];    // layout A: index r*16 + sub, d = (r<<4)|sub
    __shared__ u64    s_d2a[256];   // layout B: index r*16 + sub, d = (sub<<4)|r
    __shared__ u64    s_d2b[256];
    __shared__ float2 s_cs1[8], s_cs2[8];

    int t = threadIdx.x;
    // ---- per-block setup (bits[d,i] = (d >> (7-i)) & 1) ----
#pragma unroll
    for (int d = t; d < 256; d += 128) {
        float e1 = 0.f, e2 = 0.f;
#pragma unroll
        for (int i = 0; i < 8; i++) {
            float bc  = (float)((d >> (7 - i)) & 1);
            int   t1  = (i + 1) & 7;
            int   t2  = (i + 7) & 7;
            float bt1 = (float)((d >> (7 - t1)) & 1);
            float bt2 = (float)((d >> (7 - t2)) & 1);
            e1 += bc * (bt1 - 0.5f) * crz1[i];
            e2 += bc * (bt2 - 0.5f) * crz2[i];
        }
        float s, c;
        __sincosf(e1, &s, &c);
        s_d1[d] = pack2(c, s);
        __sincosf(e2, &s, &c);
        int tb = (d & 15) * 16 + (d >> 4);   // transposed for layout B reads
        s_d2a[tb] = pack2(c, s);
        s_d2b[tb] = pack2(-s, c);
    }
    if (t < 8) {
        float s, c;
        __sincosf(0.5f * ry1[t], &s, &c); s_cs1[t] = make_float2(c, s);
        __sincosf(0.5f * ry2[t], &s, &c); s_cs2[t] = make_float2(c, s);
    }
    __syncthreads();

    int tid  = blockIdx.x * blockDim.x + t;
    int warp = tid >> 5;
    int lane = t & 31;
    int sub  = lane & 15;
    int gsel = (lane >> 4) << 3;     // 0 for group 0, 8 for group 1
    if (warp * 2 < nstates) {
        // ---- encoder: coalesced load, fast sincos, broadcast in group ----
        float xv = x[warp * 16 + sub];   // sub -> (state = sub>>3, wire = sub&7)
        float s0, c0;
        __sincosf(0.5f * xv, &s0, &c0);
        float ec[8], es[8];
#pragma unroll
        for (int i = 0; i < 8; i++) {
            ec[i] = __shfl_sync(FULL, c0, gsel | i);
            es[i] = __shfl_sync(FULL, s0, gsel | i);
        }

        // ---- initial product state (layout A), fused with diag1 ----
        float plane = ((sub & 8) ? es[4] : ec[4]) *
                      (((sub & 4) ? es[5] : ec[5]) *
                       (((sub & 2) ? es[6] : ec[6]) * ((sub & 1) ? es[7] : ec[7])));
        float f01[4], f23[4];
#pragma unroll
        for (int j = 0; j < 4; j++) {
            f01[j] = (((j & 2) ? es[0] : ec[0]) * ((j & 1) ? es[1] : ec[1])) * plane;
            f23[j] = ((j & 2) ? es[2] : ec[2]) * ((j & 1) ? es[3] : ec[3]);
        }
        u64 a[16];
#pragma unroll
        for (int r = 0; r < 16; r++) {
            float amp = f01[r >> 2] * f23[r & 3];
            a[r] = mul2(pack2(amp, amp), s_d1[r * 16 + sub]);
        }

        // ---- RY1 layer (A -> B) ----
        layer_A_to_B(a, s_cs1, sub);

        // ---- diag2 in layout B: res = (x,x)*(c,s) + (y,y)*(-s,c) ----
#pragma unroll
        for (int r = 0; r < 16; r++) {
            float2 f = unpack2(a[r]);
            int idx = r * 16 + sub;
            a[r] = fma2(pack2(f.x, f.x), s_d2a[idx],
                        mul2(pack2(f.y, f.y), s_d2b[idx]));
        }

        // ---- RY2 layer (B -> A) ----
        layer_B_to_A(a, s_cs2, sub);

        // ---- measurement (layout A): out[w] = sum_d sign * |psi_d|^2 ----
        float p[16];
#pragma unroll
        for (int r = 0; r < 16; r++) {
            float2 f = unpack2(a[r]);
            p[r] = f.x * f.x + f.y * f.y;
        }
        // tree over r bits: bit0<->wire3, bit1<->wire2, bit2<->wire1, bit3<->wire0
        float o0, o1 = 0.f, o2 = 0.f, o3 = 0.f, T;
        float l1[8];
#pragma unroll
        for (int i = 0; i < 8; i++) { l1[i] = p[2*i] + p[2*i+1];  o3 += p[2*i] - p[2*i+1]; }
        float l2[4];
#pragma unroll
        for (int i = 0; i < 4; i++) { l2[i] = l1[2*i] + l1[2*i+1]; o2 += l1[2*i] - l1[2*i+1]; }
        float l3[2];
#pragma unroll
        for (int i = 0; i < 2; i++) { l3[i] = l2[2*i] + l2[2*i+1]; o1 += l2[2*i] - l2[2*i+1]; }
        o0 = l3[0] - l3[1];
        T  = l3[0] + l3[1];

        // sum o0..o3 across the 16 lanes of the group
#pragma unroll
        for (int m = 1; m < 16; m <<= 1) {
            o0 += __shfl_xor_sync(FULL, o0, m);
            o1 += __shfl_xor_sync(FULL, o1, m);
            o2 += __shfl_xor_sync(FULL, o2, m);
            o3 += __shfl_xor_sync(FULL, o3, m);
        }
        // signed Walsh butterfly on T over the 4 sub bits:
        // lane with sub = 1<<q holds wire (7-q)'s expectation
        float h = T;
#pragma unroll
        for (int q = 0; q < 4; q++) {
            float o = __shfl_xor_sync(FULL, h, 1 << q);
            h = (lane & (1 << q)) ? (o - h) : (h + o);
        }
        int gb = lane & 16;
        float v4 = __shfl_sync(FULL, h, gb | 8);
        float v5 = __shfl_sync(FULL, h, gb | 4);
        float v6 = __shfl_sync(FULL, h, gb | 2);
        float v7 = __shfl_sync(FULL, h, gb | 1);

        if (sub < 8) {
            float v;
            switch (sub) {
                case 0: v = o0; break;
                case 1: v = o1; break;
                case 2: v = o2; break;
                case 3: v = o3; break;
                case 4: v = v4; break;
                case 5: v = v5; break;
                case 6: v = v6; break;
                default: v = v7; break;
            }
            out[warp * 16 + gsel + sub] = v;   // coalesced 16 floats / warp
        }
    }
}

extern "C" void kernel_launch(void* const* d_in, const int* in_sizes, int n_in,
                              void* d_out, int out_size) {
    const float* x    = (const float*)d_in[0];  // input_features (4,4096,8)
    const float* ry1  = (const float*)d_in[1];  // params_ry1 (1,8)
    const float* crz1 = (const float*)d_in[2];  // params_crz1 (1,8)
    const float* ry2  = (const float*)d_in[3];  // params_ry2 (1,8)
    const float* crz2 = (const float*)d_in[4];  // params_crz2 (1,8)
    float* out = (float*)d_out;

    int nstates = in_sizes[0] / 8;              // 16384

    // 2 states per warp, 4 warps per block -> 8 states per block
    int blocks = (nstates + 7) / 8;
    vqc_main<<<blocks, 128>>>(x, ry1, crz1, ry2, crz2, out, nstates);
}

// round 6
// speedup vs baseline: 1.0949x; 1.0949x over previous
#include <cuda_runtime.h>
#include <cuda_bf16.h>

#define FULL 0xffffffffu
typedef unsigned long long u64;

// ---------- packed f32x2 helpers (SASS FFMA2 path, PTX-only) ----------
__device__ __forceinline__ u64 pack2(float x, float y) {
    u64 r; asm("mov.b64 %0, {%1, %2};" : "=l"(r) : "f"(x), "f"(y)); return r;
}
__device__ __forceinline__ float2 unpack2(u64 v) {
    float2 f; asm("mov.b64 {%0, %1}, %2;" : "=f"(f.x), "=f"(f.y) : "l"(v)); return f;
}
__device__ __forceinline__ u64 mul2(u64 a, u64 b) {
    u64 d; asm("mul.rn.f32x2 %0, %1, %2;" : "=l"(d) : "l"(a), "l"(b)); return d;
}
__device__ __forceinline__ u64 fma2(u64 a, u64 b, u64 c) {
    u64 d; asm("fma.rn.f32x2 %0, %1, %2, %3;" : "=l"(d) : "l"(a), "l"(b), "l"(c)); return d;
}

// Precomputed per-launch constants (params only). __device__ globals (no alloc).
__device__ u64    g_diag1[256];    // packed (cos, sin) of CRZ block 1 phase
__device__ u64    g_diag2a[256];   // packed ( c,  s) of CRZ block 2 phase
__device__ u64    g_diag2b[256];   // packed (-s,  c)
__device__ float2 g_cs1[8];        // (cos, sin) of ry1[i]/2
__device__ float2 g_cs2[8];        // (cos, sin) of ry2[i]/2

// bits[d, i] = (d >> (7-i)) & 1  (wire i <-> bit 7-i of basis index d)
__global__ void vqc_setup(const float* __restrict__ crz1,
                          const float* __restrict__ crz2,
                          const float* __restrict__ ry1,
                          const float* __restrict__ ry2) {
    int d = threadIdx.x;  // 0..255
    float e1 = 0.f, e2 = 0.f;
#pragma unroll
    for (int i = 0; i < 8; i++) {
        float bc  = (float)((d >> (7 - i)) & 1);
        int   t1  = (i + 1) & 7;
        int   t2  = (i + 7) & 7;
        float bt1 = (float)((d >> (7 - t1)) & 1);
        float bt2 = (float)((d >> (7 - t2)) & 1);
        e1 += bc * (bt1 - 0.5f) * crz1[i];
        e2 += bc * (bt2 - 0.5f) * crz2[i];
    }
    float s, c;
    __sincosf(e1, &s, &c);
    g_diag1[d]  = pack2(c, s);
    __sincosf(e2, &s, &c);
    g_diag2a[d] = pack2(c, s);
    g_diag2b[d] = pack2(-s, c);
    if (d < 8) {
        __sincosf(0.5f * ry1[d], &s, &c); g_cs1[d] = make_float2(c, s);
        __sincosf(0.5f * ry2[d], &s, &c); g_cs2[d] = make_float2(c, s);
    }
}

// Layout: 16 lanes per state, 2 states per warp, 16 packed amps per thread.
// d = r*16 + sub, r = 0..15 in registers, sub = lane & 15.
// Wire i acts on d-bit (7-i):
//   wires 0..3 -> r bits 3..0    (in-register butterflies, pb = 8,4,2,1)
//   wires 4..7 -> sub bits 3..0  (cross-lane shfl_xor masks 8,4,2,1; stays in group)
// Pair rule (bit=0 elem a, bit=1 elem b): a' = c*a - s*b ; b' = s*a + c*b.
__device__ __forceinline__ void apply_layer(u64 a[16], const float2* cs, int sub) {
    // in-register wires 0..3
#pragma unroll
    for (int q = 0; q < 4; q++) {
        float2 p = cs[q];
        u64 c2  = pack2(p.x,  p.x);
        u64 s2  = pack2(p.y,  p.y);
        u64 ns2 = pack2(-p.y, -p.y);
        int pb = 1 << (3 - q);
#pragma unroll
        for (int r = 0; r < 16; r++) {
            if (r & pb) continue;
            int r2 = r | pb;
            u64 t  = mul2(ns2, a[r2]);
            u64 u  = mul2(s2,  a[r]);
            u64 nr = fma2(c2, a[r],  t);
            a[r2]  = fma2(c2, a[r2], u);
            a[r]   = nr;
        }
    }
    // cross-lane wires 4..7 (sub bit 7-q -> shfl mask 8,4,2,1)
#pragma unroll
    for (int q = 4; q < 8; q++) {
        float2 p = cs[q];
        int mask = 1 << (7 - q);
        u64 c2 = pack2(p.x, p.x);
        float ss = (sub & mask) ? p.y : -p.y;  // bit0: c*mine - s*other ; bit1: +s*other
        u64 ss2 = pack2(ss, ss);
#pragma unroll
        for (int r = 0; r < 16; r++) {
            float2 f = unpack2(a[r]);
            float ox = __shfl_xor_sync(FULL, f.x, mask);
            float oy = __shfl_xor_sync(FULL, f.y, mask);
            a[r] = fma2(c2, a[r], mul2(ss2, pack2(ox, oy)));
        }
    }
}

__global__ __launch_bounds__(64, 16)
void vqc_main(const float* __restrict__ x, float* __restrict__ out, int nstates) {
    int tid  = blockIdx.x * blockDim.x + threadIdx.x;
    int warp = tid >> 5;
    int lane = threadIdx.x & 31;
    int sub  = lane & 15;
    int gsel = (lane >> 4) << 3;     // 0 for group 0, 8 for group 1
    if (warp * 2 >= nstates) return;

    // ---- encoder: every lane loads (duplicated across groups, in bounds) ----
    float xv = x[warp * 16 + sub];   // sub -> (state = sub>>3, wire = sub&7)
    float s0, c0;
    __sincosf(0.5f * xv, &s0, &c0);
    // wire i of my group's state lives at source lane gsel + i
    float ec[8], es[8];
#pragma unroll
    for (int i = 0; i < 8; i++) {
        ec[i] = __shfl_sync(FULL, c0, gsel | i);
        es[i] = __shfl_sync(FULL, s0, gsel | i);
    }

    // ---- initial product state, fused with diag1 ----
    // amp(d) = prod_i (bit(7-i,d) ? sin(x_i/2) : cos(x_i/2))
    float plane = ((sub & 8) ? es[4] : ec[4]) *
                  (((sub & 4) ? es[5] : ec[5]) *
                   (((sub & 2) ? es[6] : ec[6]) * ((sub & 1) ? es[7] : ec[7])));
    float f01[4], f23[4];
#pragma unroll
    for (int j = 0; j < 4; j++) {
        f01[j] = (((j & 2) ? es[0] : ec[0]) * ((j & 1) ? es[1] : ec[1])) * plane;
        f23[j] = ((j & 2) ? es[2] : ec[2]) * ((j & 1) ? es[3] : ec[3]);
    }
    u64 a[16];
#pragma unroll
    for (int r = 0; r < 16; r++) {
        float amp = f01[r >> 2] * f23[r & 3];
        a[r] = mul2(pack2(amp, amp), g_diag1[r * 16 + sub]);
    }

    // ---- RY1 layer ----
    apply_layer(a, g_cs1, sub);

    // ---- diag2: complex multiply, packed: res = (x,x)*(c,s) + (y,y)*(-s,c) ----
#pragma unroll
    for (int r = 0; r < 16; r++) {
        float2 f = unpack2(a[r]);
        int d = r * 16 + sub;
        a[r] = fma2(pack2(f.x, f.x), g_diag2a[d],
                    mul2(pack2(f.y, f.y), g_diag2b[d]));
    }

    // ---- RY2 layer ----
    apply_layer(a, g_cs2, sub);

    // ---- measurement: out[w] = sum_d (1 - 2*bit(7-w,d)) * |psi_d|^2 ----
    float p[16];
#pragma unroll
    for (int r = 0; r < 16; r++) {
        float2 f = unpack2(a[r]);
        p[r] = f.x * f.x + f.y * f.y;
    }
    // tree over r bits: bit0<->wire3, bit1<->wire2, bit2<->wire1, bit3<->wire0
    float o0, o1 = 0.f, o2 = 0.f, o3 = 0.f, T;
    float l1[8];
#pragma unroll
    for (int i = 0; i < 8; i++) { l1[i] = p[2*i] + p[2*i+1];  o3 += p[2*i] - p[2*i+1]; }
    float l2[4];
#pragma unroll
    for (int i = 0; i < 4; i++) { l2[i] = l1[2*i] + l1[2*i+1]; o2 += l1[2*i] - l1[2*i+1]; }
    float l3[2];
#pragma unroll
    for (int i = 0; i < 2; i++) { l3[i] = l2[2*i] + l2[2*i+1]; o1 += l2[2*i] - l2[2*i+1]; }
    o0 = l3[0] - l3[1];
    T  = l3[0] + l3[1];

    // sum o0..o3 across the 16 lanes of the group (masks stay in group)
#pragma unroll
    for (int m = 1; m < 16; m <<= 1) {
        o0 += __shfl_xor_sync(FULL, o0, m);
        o1 += __shfl_xor_sync(FULL, o1, m);
        o2 += __shfl_xor_sync(FULL, o2, m);
        o3 += __shfl_xor_sync(FULL, o3, m);
    }
    // signed Walsh butterfly on T over the 4 sub bits:
    // lane with sub = 1<<q holds wire (7-q)'s expectation
    float h = T;
#pragma unroll
    for (int q = 0; q < 4; q++) {
        float o = __shfl_xor_sync(FULL, h, 1 << q);
        h = (lane & (1 << q)) ? (o - h) : (h + o);
    }
    int gb = lane & 16;
    float v4 = __shfl_sync(FULL, h, gb | 8);
    float v5 = __shfl_sync(FULL, h, gb | 4);
    float v6 = __shfl_sync(FULL, h, gb | 2);
    float v7 = __shfl_sync(FULL, h, gb | 1);

    if (sub < 8) {
        float v;
        switch (sub) {
            case 0: v = o0; break;
            case 1: v = o1; break;
            case 2: v = o2; break;
            case 3: v = o3; break;
            case 4: v = v4; break;
            case 5: v = v5; break;
            case 6: v = v6; break;
            default: v = v7; break;
        }
        // (state = lane>>4, wire = sub) -> contiguous 16 floats per warp
        out[warp * 16 + gsel + sub] = v;
    }
}

extern "C" void kernel_launch(void* const* d_in, const int* in_sizes, int n_in,
                              void* d_out, int out_size) {
    const float* x    = (const float*)d_in[0];  // input_features (4,4096,8)
    const float* ry1  = (const float*)d_in[1];  // params_ry1 (1,8)
    const float* crz1 = (const float*)d_in[2];  // params_crz1 (1,8)
    const float* ry2  = (const float*)d_in[3];  // params_ry2 (1,8)
    const float* crz2 = (const float*)d_in[4];  // params_crz2 (1,8)
    float* out = (float*)d_out;

    int nstates = in_sizes[0] / 8;              // 16384

    vqc_setup<<<1, 256>>>(crz1, crz2, ry1, ry2);

    // 2 states per warp, 2 warps per block -> 4 states per block
    int blocks = (nstates + 3) / 4;
    vqc_main<<<blocks, 64>>>(x, out, nstates);
}